// round 6
// baseline (speedup 1.0000x reference)
#include <cuda_runtime.h>
#include <math.h>

#define Bq 4
#define Sq 4096
#define Hq 1024
#define NHq 16
#define Dq 64
#define Rq 2
#define SCALEq 0.125f

typedef unsigned long long ull;

// scratch (no allocation allowed)
__device__ float g_cnt[Bq*Sq*Rq];        // [b][s][r] -> float2 loads
__device__ float g_xsum[Bq*Rq*Hq];
__device__ float g_t[Bq*Hq];             // (xsum0-xsum1) @ Wk
__device__ float g_vsum[Bq*Rq*Hq];
__device__ float g_pdiff[Bq*NHq*Hq];
__device__ float g_bdiff[Bq*NHq];

// ================= k_hist: per-b histogram of both r + buffer init =================
__global__ void __launch_bounds__(512)
k_hist(const int* __restrict__ idx, const float* __restrict__ bv) {
    __shared__ int sh0[Sq];              // 16KB
    __shared__ int sh1[Sq];              // 16KB
    int b = blockIdx.x, tid = threadIdx.x;
    for (int j = tid; j < Sq; j += 512) { sh0[j] = 0; sh1[j] = 0; }
    for (int i = tid; i < Hq; i += 512) {
        g_xsum[(b*Rq + 0)*Hq + i] = 0.f;
        g_xsum[(b*Rq + 1)*Hq + i] = 0.f;
        g_t[b*Hq + i] = 0.f;
        float sv = 4096.f * bv[i];
        g_vsum[(b*Rq + 0)*Hq + i] = sv;
        g_vsum[(b*Rq + 1)*Hq + i] = sv;
    }
    __syncthreads();
    const int2* ip = (const int2*)(idx + (size_t)b * Sq * Rq);
    for (int s = tid; s < Sq; s += 512) {
        int2 p = ip[s];
        atomicAdd(&sh0[p.x], 1);
        atomicAdd(&sh1[p.y], 1);
    }
    __syncthreads();
    float2* c2 = (float2*)g_cnt + b*Sq;
    for (int j = tid; j < Sq; j += 512)
        c2[j] = make_float2((float)sh0[j], (float)sh1[j]);
}

// ================= k_xsum: xsum[b,r,:] = sum_s cnt[b,s,r]*x[b,s,:] =================
#define SCHUNKS 64
#define SROWS (Sq / SCHUNKS)             // 64
__global__ void __launch_bounds__(256)
k_xsum(const float* __restrict__ x) {
    int b = blockIdx.y, tid = threadIdx.x;
    int h4 = tid;                        // float4 col 0..255
    int s0 = blockIdx.x * SROWS;
    const float2* cnt2 = (const float2*)g_cnt + b*Sq;
    const float4* xb4 = (const float4*)(x + (size_t)b * Sq * Hq);
    float4 a0 = make_float4(0.f,0.f,0.f,0.f);
    float4 a1 = make_float4(0.f,0.f,0.f,0.f);
    #pragma unroll 8
    for (int s = s0; s < s0 + SROWS; s++) {
        float2 c = cnt2[s];
        float4 xv = xb4[(size_t)s * 256 + h4];
        a0.x += c.x*xv.x; a0.y += c.x*xv.y; a0.z += c.x*xv.z; a0.w += c.x*xv.w;
        a1.x += c.y*xv.x; a1.y += c.y*xv.y; a1.z += c.y*xv.z; a1.w += c.y*xv.w;
    }
    float* o0 = &g_xsum[(b*Rq + 0)*Hq + h4*4];
    float* o1 = &g_xsum[(b*Rq + 1)*Hq + h4*4];
    atomicAdd(o0+0, a0.x); atomicAdd(o0+1, a0.y); atomicAdd(o0+2, a0.z); atomicAdd(o0+3, a0.w);
    atomicAdd(o1+0, a1.x); atomicAdd(o1+1, a1.y); atomicAdd(o1+2, a1.z); atomicAdd(o1+3, a1.w);
}

// ================= k_proj: t = xd@Wk (y=0) ; vsum += xsum@Wv (y=1) =================
__global__ void __launch_bounds__(256)
k_proj(const float* __restrict__ Wk, const float* __restrict__ Wv) {
    __shared__ float xa[16][8];
    int tid = threadIdx.x;
    int hc = blockIdx.x * 16;
    if (blockIdx.y == 0) {
        // t[b,:] += sum_hl (xsum0-xsum1)[b][hc+hl] * Wk[hc+hl, :]
        if (tid < 64) {
            int hl = tid >> 2, b = tid & 3;
            xa[hl][b] = g_xsum[(b*Rq + 0)*Hq + hc + hl] - g_xsum[(b*Rq + 1)*Hq + hc + hl];
        }
        __syncthreads();
        float4 acc[4];
        #pragma unroll
        for (int b = 0; b < 4; b++) acc[b] = make_float4(0.f,0.f,0.f,0.f);
        const float4* W4 = (const float4*)Wk;
        #pragma unroll
        for (int hl = 0; hl < 16; hl++) {
            float4 w = W4[(size_t)(hc + hl) * 256 + tid];
            #pragma unroll
            for (int b = 0; b < 4; b++) {
                float xv = xa[hl][b];
                acc[b].x += xv*w.x; acc[b].y += xv*w.y; acc[b].z += xv*w.z; acc[b].w += xv*w.w;
            }
        }
        #pragma unroll
        for (int b = 0; b < 4; b++) {
            float* o = &g_t[b*Hq + tid*4];
            atomicAdd(o+0, acc[b].x); atomicAdd(o+1, acc[b].y);
            atomicAdd(o+2, acc[b].z); atomicAdd(o+3, acc[b].w);
        }
    } else {
        if (tid < 128) {
            int hl = tid >> 3, br = tid & 7;
            xa[hl][br] = g_xsum[br*Hq + hc + hl];
        }
        __syncthreads();
        float4 acc[8];
        #pragma unroll
        for (int br = 0; br < 8; br++) acc[br] = make_float4(0.f,0.f,0.f,0.f);
        const float4* W4 = (const float4*)Wv;
        #pragma unroll
        for (int hl = 0; hl < 16; hl++) {
            float4 w = W4[(size_t)(hc + hl) * 256 + tid];
            #pragma unroll
            for (int br = 0; br < 8; br++) {
                float xv = xa[hl][br];
                acc[br].x += xv*w.x; acc[br].y += xv*w.y; acc[br].z += xv*w.z; acc[br].w += xv*w.w;
            }
        }
        #pragma unroll
        for (int br = 0; br < 8; br++) {
            float* o = &g_vsum[br*Hq + tid*4];
            atomicAdd(o+0, acc[br].x); atomicAdd(o+1, acc[br].y);
            atomicAdd(o+2, acc[br].z); atomicAdd(o+3, acc[br].w);
        }
    }
}

// ================= k_pdiff: warp-per-Wq-row, front-batched loads =================
__global__ void __launch_bounds__(256)
k_pdiff(const float* __restrict__ Wq, const float* __restrict__ bq) {
    // grid 136: blocks 0..127 -> 1024 row-warps; blocks 128..135 -> 64 bdiff warps
    __shared__ float st[Bq*Hq];          // t staged, 16KB
    int tid = threadIdx.x;
    for (int i = tid; i < Bq*Hq; i += 256) st[i] = g_t[i];
    __syncthreads();

    int warp = tid >> 5, lane = tid & 31;
    int wg = blockIdx.x * 8 + warp;

    if (wg < 1024) {
        int h = wg;
        const float4* wr = (const float4*)(Wq + (size_t)h * Hq);
        // front-batch ALL row loads -> MLP=8 per warp
        float4 w[8];
        #pragma unroll
        for (int j = 0; j < 8; j++) w[j] = wr[j*32 + lane];

        float acc[Bq][8];
        #pragma unroll
        for (int b = 0; b < Bq; b++) {
            const float4* tb = (const float4*)&st[b*Hq];
            #pragma unroll
            for (int j = 0; j < 8; j++) {
                float4 tv = tb[j*32 + lane];     // head n = 2j + (lane>>4)
                acc[b][j] = w[j].x*tv.x + w[j].y*tv.y + w[j].z*tv.z + w[j].w*tv.w;
            }
        }
        #pragma unroll
        for (int b = 0; b < Bq; b++)
            #pragma unroll
            for (int j = 0; j < 8; j++) {
                float v = acc[b][j];
                v += __shfl_xor_sync(0xffffffffu, v, 8);
                v += __shfl_xor_sync(0xffffffffu, v, 4);
                v += __shfl_xor_sync(0xffffffffu, v, 2);
                v += __shfl_xor_sync(0xffffffffu, v, 1);
                acc[b][j] = v;
            }
        if ((lane & 15) == 0) {
            int half = lane >> 4;
            #pragma unroll
            for (int b = 0; b < Bq; b++)
                #pragma unroll
                for (int j = 0; j < 8; j++)
                    g_pdiff[(b*NHq + (2*j + half))*Hq + h] = SCALEq * acc[b][j];
        }
    } else if (wg < 1024 + Bq*NHq) {
        int id = wg - 1024;
        int b = id >> 4, n = id & 15;
        float s = bq[n*Dq + lane]      * st[b*Hq + n*Dq + lane]
                + bq[n*Dq + 32 + lane] * st[b*Hq + n*Dq + 32 + lane];
        #pragma unroll
        for (int o = 16; o > 0; o >>= 1) s += __shfl_xor_sync(0xffffffffu, s, o);
        if (lane == 0) g_bdiff[b*NHq + n] = SCALEq * s;
    }
}

// ================= k_main: scores (f32x2) -> sigmoid -> blend v =================
#define SMEM_MAIN ((NHq*Hq + 2*Hq + 16) * sizeof(float))
__global__ void __launch_bounds__(128, 2)
k_main(const float* __restrict__ x, float* __restrict__ out) {
    extern __shared__ float sm[];
    float* sPd = sm;                 // [16][1024]
    float* sV0 = sm + NHq*Hq;        // [1024]
    float* sV1 = sV0 + Hq;           // [1024]
    float* sBd = sV1 + Hq;           // [16]

    int b = blockIdx.y;
    {
        const float4* gp4 = (const float4*)&g_pdiff[b*NHq*Hq];
        float4* sp4 = (float4*)sPd;
        for (int i = threadIdx.x; i < NHq*Hq/4; i += 128) sp4[i] = gp4[i];
        const float4* v0g = (const float4*)&g_vsum[(b*Rq + 0)*Hq];
        const float4* v1g = (const float4*)&g_vsum[(b*Rq + 1)*Hq];
        float4* s04 = (float4*)sV0; float4* s14 = (float4*)sV1;
        for (int i = threadIdx.x; i < Hq/4; i += 128) { s04[i] = v0g[i]; s14[i] = v1g[i]; }
        if (threadIdx.x < NHq) sBd[threadIdx.x] = g_bdiff[b*NHq + threadIdx.x];
    }
    __syncthreads();

    int warp = threadIdx.x >> 5, lane = threadIdx.x & 31;
    int r0 = blockIdx.x * 16 + warp * 4;
    const float* xb = x + (size_t)b * Sq * Hq;
    float* ob = out + (size_t)b * Sq * Hq;

    const double2* xr[4];
    #pragma unroll
    for (int i = 0; i < 4; i++)
        xr[i] = (const double2*)(xb + (size_t)(r0 + i) * Hq);
    const double2* sPdD = (const double2*)sPd;

    ull acc[4][NHq];
    #pragma unroll
    for (int i = 0; i < 4; i++)
        #pragma unroll
        for (int n = 0; n < NHq; n++) acc[i][n] = 0ull;

    double2 xa[4], xb2[4], xc[4];
    #pragma unroll
    for (int i = 0; i < 4; i++) { xa[i] = xr[i][lane]; xb2[i] = xr[i][lane + 32]; }

    #pragma unroll
    for (int j = 0; j < 8; j++) {
        int h4 = lane + 32*j;
        if (j < 6) {
            #pragma unroll
            for (int i = 0; i < 4; i++) xc[i] = xr[i][h4 + 64];
        }
        ull xlo[4], xhi[4];
        #pragma unroll
        for (int i = 0; i < 4; i++) {
            xlo[i] = __double_as_longlong(xa[i].x);
            xhi[i] = __double_as_longlong(xa[i].y);
        }
        #pragma unroll
        for (int n = 0; n < NHq; n++) {
            double2 pdv = sPdD[n*256 + h4];
            ull plo = __double_as_longlong(pdv.x);
            ull phi = __double_as_longlong(pdv.y);
            #pragma unroll
            for (int i = 0; i < 4; i++) {
                asm("fma.rn.f32x2 %0, %1, %2, %0;" : "+l"(acc[i][n]) : "l"(xlo[i]), "l"(plo));
                asm("fma.rn.f32x2 %0, %1, %2, %0;" : "+l"(acc[i][n]) : "l"(xhi[i]), "l"(phi));
            }
        }
        #pragma unroll
        for (int i = 0; i < 4; i++) { xa[i] = xb2[i]; xb2[i] = xc[i]; }
    }

    float prob[4][NHq];
    #pragma unroll
    for (int i = 0; i < 4; i++)
        #pragma unroll
        for (int n = 0; n < NHq; n++) {
            ull a = acc[i][n];
            float v = __uint_as_float((unsigned)(a & 0xffffffffu))
                    + __uint_as_float((unsigned)(a >> 32));
            v += __shfl_xor_sync(0xffffffffu, v, 16);
            v += __shfl_xor_sync(0xffffffffu, v, 8);
            v += __shfl_xor_sync(0xffffffffu, v, 4);
            v += __shfl_xor_sync(0xffffffffu, v, 2);
            v += __shfl_xor_sync(0xffffffffu, v, 1);
            prob[i][n] = 1.f / (1.f + __expf(-(v + sBd[n])));
        }

    const float4* v04 = (const float4*)sV0;
    const float4* v14 = (const float4*)sV1;
    #pragma unroll
    for (int i = 0; i < 4; i++) {
        float4* o4 = (float4*)(ob + (size_t)(r0 + i) * Hq);
        #pragma unroll
        for (int j = 0; j < 8; j++) {
            int h4 = lane + 32*j;
            float ppA = prob[i][2*j];
            float ppB = prob[i][2*j + 1];
            float pp = (lane & 16) ? ppB : ppA;
            float4 a = v04[h4];
            float4 c = v14[h4];
            float4 o;
            o.x = c.x + pp * (a.x - c.x);
            o.y = c.y + pp * (a.y - c.y);
            o.z = c.z + pp * (a.z - c.z);
            o.w = c.w + pp * (a.w - c.w);
            o4[h4] = o;
        }
    }
}

extern "C" void kernel_launch(void* const* d_in, const int* in_sizes, int n_in,
                              void* d_out, int out_size) {
    const float* x  = (const float*)d_in[0];
    // d_in[1] attention_mask: unused by reference
    const float* Wq = (const float*)d_in[2];
    const float* bq = (const float*)d_in[3];
    const float* Wk = (const float*)d_in[4];
    // d_in[5] bk cancels in the score difference
    const float* Wv = (const float*)d_in[6];
    const float* bv = (const float*)d_in[7];
    const int* idx  = (const int*)d_in[8];
    float* out = (float*)d_out;

    cudaFuncSetAttribute(k_main, cudaFuncAttributeMaxDynamicSharedMemorySize, (int)SMEM_MAIN);

    k_hist<<<Bq, 512>>>(idx, bv);
    k_xsum<<<dim3(SCHUNKS, Bq), 256>>>(x);
    k_proj<<<dim3(64, 2), 256>>>(Wk, Wv);
    k_pdiff<<<136, 256>>>(Wq, bq);
    k_main<<<dim3(Sq/16, Bq), 128, SMEM_MAIN>>>(x, out);
}